// round 9
// baseline (speedup 1.0000x reference)
#include <cuda_runtime.h>
#include <cuda_bf16.h>
#include <math.h>

#define Fn 500
#define Hn 2000
#define FH 2500
#define Dn 64
#define Bn 4096
#define NW 80            // bitmask words per row (80*32 = 2560 >= 2500)
#define NJC 4            // j-chunks of 640 bits

// Scratch
__device__ __align__(16) float g_U[Fn * 128];        // [P1(=wu*a^2) | P2(=wu*a)]
__device__ __align__(16) float g_V[FH * 128];        // [b | b^2]
__device__ float g_B[FH];
__device__ __align__(16) float g_pre_f[Fn * Dn];
__device__ unsigned g_mbits[Fn * NW];
__device__ __align__(16) float g_ctx_part[NJC][Fn][Dn];
__device__ float g_ssum_part[Fn][NJC];
__device__ __align__(16) float g_ctx[Fn * Dn];
__device__ int g_maxa_bits = 0;   // idempotent across replays (same inputs)
__device__ int g_maxb_bits = 0;

typedef unsigned long long ull;
__device__ __forceinline__ ull pk2(float a, float b) {
    ull r; asm("mov.b64 %0, {%1,%2};" : "=l"(r) : "f"(a), "f"(b)); return r;
}
__device__ __forceinline__ void upk2(ull v, float& a, float& b) {
    asm("mov.b64 {%0,%1}, %2;" : "=f"(a), "=f"(b) : "l"(v));
}
__device__ __forceinline__ ull f2fma(ull a, ull b, ull c) {
    ull d; asm("fma.rn.f32x2 %0, %1, %2, %3;" : "=l"(d) : "l"(a), "l"(b), "l"(c)); return d;
}
__device__ __forceinline__ const float* full_row(const float* feat,
                                                 const float* hid, int j) {
    return (j < Fn) ? (feat + j * Dn) : (hid + (j - Fn) * Dn);
}

// ---------------------------------------------------------------------------
// K1: blocks 0..624: pre_w rows -> V=[b,b^2], B_j, maxb
//     blocks 625..749: pre_f rows -> U=[wu*a^2, wu*a], pre_f, maxa
//     blocks 750..906: mask -> bitmask (thread-per-word, 32 scalar loads)
// ---------------------------------------------------------------------------
__global__ __launch_bounds__(256) void k1(const float* __restrict__ feat,
                                          const float* __restrict__ hid,
                                          const float* __restrict__ Ww,
                                          const float* __restrict__ bw,
                                          const float* __restrict__ Wu,
                                          const float* __restrict__ mask)
{
    __shared__ float sx[4][Dn];
    __shared__ float s_red[8];
    __shared__ float s_rmax[8];

    const int blk  = blockIdx.x;
    const int tid  = threadIdx.x;
    const int g    = tid >> 6;
    const int a    = tid & 63;
    const int wid  = tid >> 5;
    const int lane = tid & 31;

    if (blk < 625) {
        const int row = blk * 4 + g;                    // j: 0..2499
        float v = (row < Fn) ? feat[row * Dn + a] : hid[(row - Fn) * Dn + a];
        sx[g][a] = v;
        __syncthreads();
        float bacc = 0.f;
        #pragma unroll
        for (int k = 0; k < Dn; k++)
            bacc += sx[g][k] * __ldg(&Ww[(Dn + k) * Dn + a]);
        const float wua = __ldg(&Wu[a]);
        const float b2 = bacc * bacc;
        g_V[row * 128 + a]      = bacc;
        g_V[row * 128 + 64 + a] = b2;
        float term = wua * (bacc - bacc * b2 * 0.33333334f);
        float mm = fabsf(bacc);
        #pragma unroll
        for (int off = 16; off > 0; off >>= 1) {
            term += __shfl_xor_sync(0xffffffffu, term, off);
            mm = fmaxf(mm, __shfl_xor_sync(0xffffffffu, mm, off));
        }
        if (lane == 0) { s_red[wid] = term; s_rmax[wid] = mm; }
        __syncthreads();
        if (tid < 4)
            g_B[blk * 4 + tid] = s_red[2 * tid] + s_red[2 * tid + 1];
        if (tid == 0) {
            float mx = fmaxf(fmaxf(s_rmax[0], s_rmax[1]),
                             fmaxf(s_rmax[2], s_rmax[3]));
            mx = fmaxf(mx, fmaxf(fmaxf(s_rmax[4], s_rmax[5]),
                                 fmaxf(s_rmax[6], s_rmax[7])));
            atomicMax(&g_maxb_bits, __float_as_int(mx));
        }
    } else if (blk < 750) {
        const int row = (blk - 625) * 4 + g;            // i: 0..499
        sx[g][a] = feat[row * Dn + a];
        __syncthreads();
        float av = __ldg(&bw[a]);
        #pragma unroll
        for (int k = 0; k < Dn; k++)
            av += sx[g][k] * __ldg(&Ww[k * Dn + a]);
        const float wua = __ldg(&Wu[a]);
        g_pre_f[row * Dn + a]   = av;
        g_U[row * 128 + a]      = wua * av * av;       // P1
        g_U[row * 128 + 64 + a] = wua * av;            // P2
        float mm = fabsf(av);
        #pragma unroll
        for (int off = 16; off > 0; off >>= 1)
            mm = fmaxf(mm, __shfl_xor_sync(0xffffffffu, mm, off));
        if (lane == 0) s_rmax[wid] = mm;
        __syncthreads();
        if (tid == 0) {
            float mx = fmaxf(fmaxf(s_rmax[0], s_rmax[1]),
                             fmaxf(s_rmax[2], s_rmax[3]));
            mx = fmaxf(mx, fmaxf(fmaxf(s_rmax[4], s_rmax[5]),
                                 fmaxf(s_rmax[6], s_rmax[7])));
            atomicMax(&g_maxa_bits, __float_as_int(mx));
        }
    } else {
        // bitmask build: one word (32 j's) per thread
        const int gw = (blk - 750) * 256 + tid;         // 0..40191
        if (gw < Fn * NW) {
            const int i = gw / NW;
            const int w = gw - i * NW;
            const int j0 = w * 32;
            const float* mrow = mask + (size_t)i * FH;
            unsigned word = 0;
            #pragma unroll
            for (int t = 0; t < 32; t++) {
                int j = j0 + t;
                if (j < FH && __ldg(&mrow[j]) != 0.0f) word |= (1u << t);
            }
            g_mbits[gw] = word;
        }
    }
}

// ---------------------------------------------------------------------------
// K2: 2000 blocks = 500 i x 4 j-chunks (640 j each). 128 threads.
// Compaction from smem bitmask; thread-per-item bilinear; partial ctx/ssum.
// ---------------------------------------------------------------------------
__global__ __launch_bounds__(128) void k2(const float* __restrict__ feat,
                                          const float* __restrict__ hid,
                                          const float* __restrict__ Wu)
{
    __shared__ __align__(16) float s_U[128];
    __shared__ __align__(16) float s_pf[Dn];
    __shared__ __align__(16) float s_wu[Dn];
    __shared__ unsigned s_words[20];
    __shared__ unsigned short s_jlist[640];
    __shared__ float s_elist[640];
    __shared__ int   s_warpbase[5];
    __shared__ float s_wsum[4];
    __shared__ float s_part[2][Dn];
    __shared__ float s_swu;
    __shared__ int   s_exact;

    const int i    = blockIdx.x >> 2;
    const int jc   = blockIdx.x & 3;
    const int jbase = jc * 640;
    const int tid  = threadIdx.x;
    const int wid  = tid >> 5;
    const int lane = tid & 31;

    s_U[tid] = g_U[i * 128 + tid];
    if (tid < 20) s_words[tid] = g_mbits[i * NW + jc * 20 + tid];
    if (tid < Dn) {
        s_pf[tid] = g_pre_f[i * Dn + tid];
        s_wu[tid] = __ldg(&Wu[tid]);
    }
    __syncthreads();

    if (wid == 0) {
        float s = fabsf(s_wu[lane]) + fabsf(s_wu[lane + 32]);
        #pragma unroll
        for (int off = 16; off > 0; off >>= 1)
            s += __shfl_xor_sync(0xffffffffu, s, off);
        if (lane == 0) s_swu = s;
    }
    __syncthreads();
    if (tid == 0) {
        float bnd = __int_as_float(g_maxa_bits) + __int_as_float(g_maxb_bits);
        float b5 = bnd * bnd; b5 = b5 * b5 * bnd;
        s_exact = (0.1333334f * b5 * s_swu >= 1e-4f) ? 1 : 0;
    }

    // ---- compaction: 5 chunks of 128 local j's (bits from smem)
    unsigned flags = 0;
    #pragma unroll
    for (int c = 0; c < 5; c++) {
        const int jl = c * 128 + tid;               // 0..639
        const bool act = ((s_words[jl >> 5] >> (jl & 31)) & 1u) &&
                         (jbase + jl < FH);
        if (act) flags |= (1u << c);
    }
    const int cl = __popc(flags);
    int inc = cl;
    #pragma unroll
    for (int off = 1; off < 32; off <<= 1) {
        int v = __shfl_up_sync(0xffffffffu, inc, off);
        if (lane >= off) inc += v;
    }
    if (lane == 31) s_warpbase[wid + 1] = inc;
    __syncthreads();
    if (tid == 0) {
        s_warpbase[0] = 0;
        #pragma unroll
        for (int w = 1; w <= 4; w++) s_warpbase[w] += s_warpbase[w - 1];
    }
    __syncthreads();
    {
        int off = s_warpbase[wid] + inc - cl;
        #pragma unroll
        for (int c = 0; c < 5; c++)
            if ((flags >> c) & 1u)
                s_jlist[off++] = (unsigned short)(c * 128 + tid);
    }
    __syncthreads();
    const int cnt = s_warpbase[4];

    // ---- Phase B: thread-per-item
    float wsum = 0.f;
    if (!s_exact) {
        const ull* P1u = (const ull*)s_U;            // pairs of P1
        const ull* P2u = (const ull*)(s_U + 64);     // pairs of P2
        for (int m = tid; m < cnt; m += 128) {
            const int j = jbase + (int)s_jlist[m];
            const float4* vr = (const float4*)(g_V + j * 128);   // b half
            ull acc = 0ull;
            #pragma unroll
            for (int q = 0; q < 16; q++) {
                float4 b4 = __ldg(vr + q);
                ull b01 = pk2(b4.x, b4.y);
                ull b23 = pk2(b4.z, b4.w);
                ull t01 = f2fma(P2u[2 * q],     b01, P1u[2 * q]);
                ull t23 = f2fma(P2u[2 * q + 1], b23, P1u[2 * q + 1]);
                acc = f2fma(t01, b01, acc);
                acc = f2fma(t23, b23, acc);
            }
            float d0, d1; upk2(acc, d0, d1);
            float e = __expf(__ldg(&g_B[j]) - (d0 + d1));
            s_elist[m] = e;
            wsum += e;
        }
    } else {
        for (int m = tid; m < cnt; m += 128) {
            const int j = jbase + (int)s_jlist[m];
            const float* vr = g_V + j * 128;         // b values
            float s = 0.f;
            for (int k = 0; k < Dn; k++)
                s += tanhf(s_pf[k] + vr[k]) * s_wu[k];
            float e = expf(s);
            s_elist[m] = e;
            wsum += e;
        }
    }
    #pragma unroll
    for (int off = 16; off > 0; off >>= 1)
        wsum += __shfl_xor_sync(0xffffffffu, wsum, off);
    if (lane == 0) s_wsum[wid] = wsum;
    __syncthreads();
    if (tid == 0)
        g_ssum_part[i][jc] = (s_wsum[0] + s_wsum[1]) + (s_wsum[2] + s_wsum[3]);

    // ---- Phase C: partial ctx (2 groups x 64 cols, 8 chains)
    {
        const int gg = tid >> 6;
        const int k  = tid & 63;
        float a0 = 0.f, a1 = 0.f, a2 = 0.f, a3 = 0.f;
        float a4 = 0.f, a5 = 0.f, a6 = 0.f, a7 = 0.f;
        int m = gg;
        for (; m + 14 < cnt; m += 16) {
            a0 += s_elist[m]      * __ldg(full_row(feat, hid, jbase + (int)s_jlist[m])      + k);
            a1 += s_elist[m + 2]  * __ldg(full_row(feat, hid, jbase + (int)s_jlist[m + 2])  + k);
            a2 += s_elist[m + 4]  * __ldg(full_row(feat, hid, jbase + (int)s_jlist[m + 4])  + k);
            a3 += s_elist[m + 6]  * __ldg(full_row(feat, hid, jbase + (int)s_jlist[m + 6])  + k);
            a4 += s_elist[m + 8]  * __ldg(full_row(feat, hid, jbase + (int)s_jlist[m + 8])  + k);
            a5 += s_elist[m + 10] * __ldg(full_row(feat, hid, jbase + (int)s_jlist[m + 10]) + k);
            a6 += s_elist[m + 12] * __ldg(full_row(feat, hid, jbase + (int)s_jlist[m + 12]) + k);
            a7 += s_elist[m + 14] * __ldg(full_row(feat, hid, jbase + (int)s_jlist[m + 14]) + k);
        }
        for (; m < cnt; m += 2)
            a0 += s_elist[m] * __ldg(full_row(feat, hid, jbase + (int)s_jlist[m]) + k);
        s_part[gg][k] = ((a0 + a1) + (a2 + a3)) + ((a4 + a5) + (a6 + a7));
        __syncthreads();
        if (tid < Dn)
            g_ctx_part[jc][i][tid] = s_part[0][tid] + s_part[1][tid];
    }
}

// ---------------------------------------------------------------------------
// K3: reduce 4 partials per row, divide by ssum. 125 blocks x 256 (4 rows).
// ---------------------------------------------------------------------------
__global__ __launch_bounds__(256) void k3()
{
    const int i = blockIdx.x * 4 + (threadIdx.x >> 6);
    const int k = threadIdx.x & 63;
    float ss = (g_ssum_part[i][0] + g_ssum_part[i][1]) +
               (g_ssum_part[i][2] + g_ssum_part[i][3]);
    const float inv = (ss > 0.f) ? (1.0f / ss) : 1.0f;
    float c = (g_ctx_part[0][i][k] + g_ctx_part[1][i][k]) +
              (g_ctx_part[2][i][k] + g_ctx_part[3][i][k]);
    g_ctx[i * Dn + k] = c * inv;
}

// ---------------------------------------------------------------------------
// K4: out = values @ ctx. 512 blocks x 8 rows, 128 threads.
// ---------------------------------------------------------------------------
__global__ __launch_bounds__(128) void k4(const float* __restrict__ values,
                                          float* __restrict__ out)
{
    __shared__ __align__(16) float s_val[8][50];
    __shared__ __align__(16) float s_ctx[50][Dn];

    const int rb   = blockIdx.x;
    const int tid  = threadIdx.x;
    const int tx   = tid & 15;
    const int ty   = tid >> 4;
    const int col0 = tx * 4;
    const int row  = rb * 8 + ty;
    ull a0 = 0ull, a1 = 0ull;

    for (int f0 = 0; f0 < Fn; f0 += 50) {
        for (int idx = tid; idx < 8 * 50; idx += 128) {
            int r = idx / 50, f = idx - r * 50;
            s_val[r][f] = values[(size_t)(rb * 8 + r) * Fn + f0 + f];
        }
        for (int idx = tid; idx < 50 * Dn; idx += 128) {
            int f = idx >> 6, c = idx & 63;
            s_ctx[f][c] = g_ctx[(f0 + f) * Dn + c];
        }
        __syncthreads();
        #pragma unroll
        for (int f = 0; f < 50; f++) {
            float v = s_val[ty][f];
            ull vp = pk2(v, v);
            const ull* cp = (const ull*)&s_ctx[f][col0];
            a0 = f2fma(vp, cp[0], a0);
            a1 = f2fma(vp, cp[1], a1);
        }
        __syncthreads();
    }
    float a, b, c, d;
    upk2(a0, a, b); upk2(a1, c, d);
    *(float4*)&out[(size_t)row * Dn + col0] = make_float4(a, b, c, d);
}

// ---------------------------------------------------------------------------
extern "C" void kernel_launch(void* const* d_in, const int* in_sizes, int n_in,
                              void* d_out, int out_size)
{
    const float* values   = (const float*)d_in[0];
    const float* feat_emb = (const float*)d_in[1];
    const float* hid_emb  = (const float*)d_in[2];
    const float* Ww       = (const float*)d_in[3];
    const float* bw       = (const float*)d_in[4];
    const float* Wu       = (const float*)d_in[5];
    const float* mask     = (const float*)d_in[6];
    float* out            = (float*)d_out;

    k1<<<907, 256>>>(feat_emb, hid_emb, Ww, bw, Wu, mask);
    k2<<<2000, 128>>>(feat_emb, hid_emb, Wu);
    k3<<<125, 256>>>();
    k4<<<512, 128>>>(values, out);
}

// round 10
// speedup vs baseline: 1.5892x; 1.5892x over previous
#include <cuda_runtime.h>
#include <cuda_bf16.h>
#include <math.h>

#define Fn 500
#define Hn 2000
#define FH 2500
#define Dn 64
#define Bn 4096
#define NB 592            // 4 CTAs/SM x 148 SMs, all co-resident
#define NCOPY 218         // blocks streaming `values`
#define NCOMP 374         // blocks doing stage1+2
#define NV4 512000        // values float4 count (4096*500/4)

// Device scratch
__device__ __align__(16) float g_values[Bn * Fn];
__device__ __align__(16) float g_U[Fn * 128];     // [P1=wu*a^2 | P2=wu*a]
__device__ __align__(16) float g_V[FH * 128];     // [b | b^2]
__device__ __align__(16) float g_full[FH * Dn];
__device__ __align__(16) float g_pre_f[Fn * Dn];
__device__ __align__(16) float g_ctx[Fn * Dn];
__device__ float g_B[FH];
__device__ int g_maxa_bits = 0;   // idempotent across replays (same inputs)
__device__ int g_maxb_bits = 0;

// Barrier state (replay-safe: counters self-reset, gens monotonic)
__device__ unsigned g_cntA = 0, g_genA = 0;   // compute-only (374)
__device__ unsigned g_cntB = 0, g_genB = 0;   // all blocks (592)

__device__ __forceinline__ void bar_sync(unsigned* cnt, unsigned* gen, unsigned n) {
    __syncthreads();
    __threadfence();
    if (threadIdx.x == 0) {
        unsigned g = *(volatile unsigned*)gen;
        if (atomicAdd(cnt, 1u) == n - 1u) {
            *cnt = 0u;
            __threadfence();
            atomicExch(gen, g + 1u);
        } else {
            while (*(volatile unsigned*)gen == g) __nanosleep(64);
        }
        __threadfence();
    }
    __syncthreads();
}

typedef unsigned long long ull;
__device__ __forceinline__ ull pk2(float a, float b) {
    ull r; asm("mov.b64 %0, {%1,%2};" : "=l"(r) : "f"(a), "f"(b)); return r;
}
__device__ __forceinline__ void upk2(ull v, float& a, float& b) {
    asm("mov.b64 {%0,%1}, %2;" : "=f"(a), "=f"(b) : "l"(v));
}
__device__ __forceinline__ ull f2fma(ull a, ull b, ull c) {
    ull d; asm("fma.rn.f32x2 %0, %1, %2, %3;" : "=l"(d) : "l"(a), "l"(b), "l"(c)); return d;
}

// Shared memory union across stages
struct __align__(16) S1s {
    float sx[2][Dn];
    float red[4];
    float rmax[4];
};
struct __align__(16) S2s {
    float elist[2560];
    unsigned short jlist[2560];
    __align__(16) float U[128];
    __align__(16) float pf[Dn];
    __align__(16) float wu[Dn];
    float part[2][Dn];
    int   warpbase[5];
    float wsum[4];
    float red4[4];
    float swu, inv;
    int   exact;
};
struct __align__(16) S3s {
    float val[8][50];
    float ctx[50][Dn];
};
union SMem { S1s s1; S2s s2; S3s s3; };

__global__ __launch_bounds__(128, 4) void fused_all(
    const float* __restrict__ values,
    const float* __restrict__ feat,
    const float* __restrict__ hid,
    const float* __restrict__ Ww,
    const float* __restrict__ bw,
    const float* __restrict__ Wu,
    const float* __restrict__ mask,
    float* __restrict__ out)
{
    __shared__ SMem sm;
    const int tid  = threadIdx.x;
    const int wid  = tid >> 5;
    const int lane = tid & 31;

    if (blockIdx.x < NCOPY) {
        // ============ COPY blocks: stream values -> g_values (max MLP) ======
        const float4* src = (const float4*)values;
        float4* dst = (float4*)g_values;
        for (int idx = blockIdx.x * 128 + tid; idx < NV4; idx += NCOPY * 128)
            dst[idx] = __ldg(&src[idx]);
    } else {
        const int b = blockIdx.x - NCOPY;     // 0..373

        // ============ Stage 1: projections (grid-stride over 750 tasks) =====
        {
            const int r = tid >> 6;   // 0/1
            const int a = tid & 63;
            for (int t = b; t < 1500; t += 2 * NCOMP) { /*unused shape*/ break; }
            for (int t = b; t < 750; t += NCOMP) {
                __syncthreads();
                if (t < 625) {
                    const int row = t * 2 + r;                 // j: 0..1249
                    // two j-rows per task covering 0..2499 via t*2+r? 625*2=1250 only!
                }
                break;
            }
            // correct task loop: 1250 j-tasks of 2 rows + 250 i-tasks of 2 rows
            for (int t = b; t < 1500; t += NCOMP) {
                __syncthreads();
                if (t < 1250) {
                    const int row = t * 2 + r;                 // j: 0..2499
                    float v = (row < Fn) ? __ldg(&feat[row * Dn + a])
                                         : __ldg(&hid[(row - Fn) * Dn + a]);
                    g_full[row * Dn + a] = v;
                    sm.s1.sx[r][a] = v;
                    __syncthreads();
                    float bb = 0.f;
                    #pragma unroll
                    for (int k = 0; k < Dn; k++)
                        bb += sm.s1.sx[r][k] * __ldg(&Ww[(Dn + k) * Dn + a]);
                    const float wua = __ldg(&Wu[a]);
                    const float b2 = bb * bb;
                    g_V[row * 128 + a]      = bb;
                    g_V[row * 128 + 64 + a] = b2;
                    float term = wua * (bb - bb * b2 * 0.33333334f);
                    float mm = fabsf(bb);
                    #pragma unroll
                    for (int off = 16; off > 0; off >>= 1) {
                        term += __shfl_xor_sync(0xffffffffu, term, off);
                        mm = fmaxf(mm, __shfl_xor_sync(0xffffffffu, mm, off));
                    }
                    if (lane == 0) { sm.s1.red[wid] = term; sm.s1.rmax[wid] = mm; }
                    __syncthreads();
                    if (tid == 0) {
                        g_B[row] = sm.s1.red[0] + sm.s1.red[1];
                        atomicMax(&g_maxb_bits,
                                  __float_as_int(fmaxf(sm.s1.rmax[0], sm.s1.rmax[1])));
                    } else if (tid == 64) {
                        g_B[row] = sm.s1.red[2] + sm.s1.red[3];
                        atomicMax(&g_maxb_bits,
                                  __float_as_int(fmaxf(sm.s1.rmax[2], sm.s1.rmax[3])));
                    }
                } else {
                    const int row = (t - 1250) * 2 + r;        // i: 0..499
                    sm.s1.sx[r][a] = __ldg(&feat[row * Dn + a]);
                    __syncthreads();
                    float av = __ldg(&bw[a]);
                    #pragma unroll
                    for (int k = 0; k < Dn; k++)
                        av += sm.s1.sx[r][k] * __ldg(&Ww[k * Dn + a]);
                    const float wua = __ldg(&Wu[a]);
                    g_pre_f[row * Dn + a]   = av;
                    g_U[row * 128 + a]      = wua * av * av;
                    g_U[row * 128 + 64 + a] = wua * av;
                    float mm = fabsf(av);
                    #pragma unroll
                    for (int off = 16; off > 0; off >>= 1)
                        mm = fmaxf(mm, __shfl_xor_sync(0xffffffffu, mm, off));
                    if (lane == 0) sm.s1.rmax[wid] = mm;
                    __syncthreads();
                    if (tid == 0)
                        atomicMax(&g_maxa_bits,
                                  __float_as_int(fmaxf(sm.s1.rmax[0], sm.s1.rmax[1])));
                    if (tid == 64)
                        atomicMax(&g_maxa_bits,
                                  __float_as_int(fmaxf(sm.s1.rmax[2], sm.s1.rmax[3])));
                }
            }
        }

        bar_sync(&g_cntA, &g_genA, NCOMP);

        // ============ Stage 2: full-row attention -> g_ctx ==================
        for (int i = b; i < Fn; i += NCOMP) {
            __syncthreads();
            for (int idx = tid; idx < 128; idx += 128)
                sm.s2.U[idx] = g_U[i * 128 + idx];
            if (tid < Dn) {
                sm.s2.pf[tid] = g_pre_f[i * Dn + tid];
                sm.s2.wu[tid] = __ldg(&Wu[tid]);
            }
            __syncthreads();
            if (wid == 0) {
                float s = fabsf(sm.s2.wu[lane]) + fabsf(sm.s2.wu[lane + 32]);
                #pragma unroll
                for (int off = 16; off > 0; off >>= 1)
                    s += __shfl_xor_sync(0xffffffffu, s, off);
                if (lane == 0) sm.s2.swu = s;
            }
            __syncthreads();
            if (tid == 0) {
                float bnd = __int_as_float(g_maxa_bits) + __int_as_float(g_maxb_bits);
                float b5 = bnd * bnd; b5 = b5 * b5 * bnd;
                sm.s2.exact = (0.1333334f * b5 * sm.s2.swu >= 1e-4f) ? 1 : 0;
            }

            // Phase A: compaction (20 chunks of 128)
            const float* mrow = mask + (size_t)i * FH;
            unsigned flags = 0;
            #pragma unroll
            for (int c = 0; c < 20; c++) {
                int j = c * 128 + tid;
                if (j < FH && __ldg(&mrow[j]) != 0.0f) flags |= (1u << c);
            }
            const int cl = __popc(flags);
            int inc = cl;
            #pragma unroll
            for (int off = 1; off < 32; off <<= 1) {
                int v = __shfl_up_sync(0xffffffffu, inc, off);
                if (lane >= off) inc += v;
            }
            if (lane == 31) sm.s2.warpbase[wid + 1] = inc;
            __syncthreads();
            if (tid == 0) {
                sm.s2.warpbase[0] = 0;
                #pragma unroll
                for (int w = 1; w <= 4; w++)
                    sm.s2.warpbase[w] += sm.s2.warpbase[w - 1];
            }
            __syncthreads();
            {
                int off = sm.s2.warpbase[wid] + inc - cl;
                #pragma unroll
                for (int c = 0; c < 20; c++)
                    if ((flags >> c) & 1u)
                        sm.s2.jlist[off++] = (unsigned short)(c * 128 + tid);
            }
            __syncthreads();
            const int cnt = sm.s2.warpbase[4];

            // Phase B: thread-per-item bilinear (or exact fallback)
            float wsum = 0.f;
            if (!sm.s2.exact) {
                const ull* P1u = (const ull*)sm.s2.U;
                const ull* P2u = (const ull*)(sm.s2.U + 64);
                for (int m = tid; m < cnt; m += 128) {
                    const int j = sm.s2.jlist[m];
                    const float4* vr = (const float4*)(g_V + j * 128);
                    ull acc = 0ull;
                    #pragma unroll
                    for (int q = 0; q < 16; q++) {
                        float4 b4 = __ldg(vr + q);
                        ull b01 = pk2(b4.x, b4.y);
                        ull b23 = pk2(b4.z, b4.w);
                        ull t01 = f2fma(P2u[2 * q],     b01, P1u[2 * q]);
                        ull t23 = f2fma(P2u[2 * q + 1], b23, P1u[2 * q + 1]);
                        acc = f2fma(t01, b01, acc);
                        acc = f2fma(t23, b23, acc);
                    }
                    float d0, d1; upk2(acc, d0, d1);
                    float e = __expf(__ldg(&g_B[j]) - (d0 + d1));
                    sm.s2.elist[m] = e;
                    wsum += e;
                }
            } else {
                for (int m = tid; m < cnt; m += 128) {
                    const int j = sm.s2.jlist[m];
                    const float* vr = g_V + j * 128;
                    float s = 0.f;
                    for (int k = 0; k < Dn; k++)
                        s += tanhf(sm.s2.pf[k] + vr[k]) * sm.s2.wu[k];
                    float e = expf(s);
                    sm.s2.elist[m] = e;
                    wsum += e;
                }
            }
            #pragma unroll
            for (int off = 16; off > 0; off >>= 1)
                wsum += __shfl_xor_sync(0xffffffffu, wsum, off);
            if (lane == 0) sm.s2.wsum[wid] = wsum;
            __syncthreads();
            if (tid == 0) {
                float ss = (sm.s2.wsum[0] + sm.s2.wsum[1]) +
                           (sm.s2.wsum[2] + sm.s2.wsum[3]);
                sm.s2.inv = (ss > 0.f) ? (1.0f / ss) : 1.0f;
            }
            __syncthreads();

            // Phase C: gather from g_full (device), 8 chains, normalize
            {
                const int gg = tid >> 6;
                const int k  = tid & 63;
                float a0 = 0.f, a1 = 0.f, a2 = 0.f, a3 = 0.f;
                float a4 = 0.f, a5 = 0.f, a6 = 0.f, a7 = 0.f;
                int m = gg;
                for (; m + 14 < cnt; m += 16) {
                    a0 += sm.s2.elist[m]      * g_full[(int)sm.s2.jlist[m]      * Dn + k];
                    a1 += sm.s2.elist[m + 2]  * g_full[(int)sm.s2.jlist[m + 2]  * Dn + k];
                    a2 += sm.s2.elist[m + 4]  * g_full[(int)sm.s2.jlist[m + 4]  * Dn + k];
                    a3 += sm.s2.elist[m + 6]  * g_full[(int)sm.s2.jlist[m + 6]  * Dn + k];
                    a4 += sm.s2.elist[m + 8]  * g_full[(int)sm.s2.jlist[m + 8]  * Dn + k];
                    a5 += sm.s2.elist[m + 10] * g_full[(int)sm.s2.jlist[m + 10] * Dn + k];
                    a6 += sm.s2.elist[m + 12] * g_full[(int)sm.s2.jlist[m + 12] * Dn + k];
                    a7 += sm.s2.elist[m + 14] * g_full[(int)sm.s2.jlist[m + 14] * Dn + k];
                }
                for (; m < cnt; m += 2)
                    a0 += sm.s2.elist[m] * g_full[(int)sm.s2.jlist[m] * Dn + k];
                sm.s2.part[gg][k] = ((a0 + a1) + (a2 + a3)) + ((a4 + a5) + (a6 + a7));
                __syncthreads();
                if (tid < Dn)
                    g_ctx[i * Dn + tid] =
                        (sm.s2.part[0][tid] + sm.s2.part[1][tid]) * sm.s2.inv;
            }
        }
    }

    bar_sync(&g_cntB, &g_genB, NB);

    // ============ Stage 3: out = g_values @ g_ctx (blocks 0..511) ===========
    if (blockIdx.x < 512) {
        const int rb   = blockIdx.x;
        const int tx   = tid & 15;
        const int ty   = tid >> 4;
        const int col0 = tx * 4;
        const int row  = rb * 8 + ty;
        ull a0 = 0ull, a1 = 0ull;

        for (int f0 = 0; f0 < Fn; f0 += 50) {
            __syncthreads();
            for (int idx = tid; idx < 8 * 50; idx += 128) {
                int r = idx / 50, f = idx - r * 50;
                sm.s3.val[r][f] = g_values[(size_t)(rb * 8 + r) * Fn + f0 + f];
            }
            for (int idx = tid; idx < 50 * Dn; idx += 128) {
                int f = idx >> 6, c = idx & 63;
                sm.s3.ctx[f][c] = g_ctx[(f0 + f) * Dn + c];
            }
            __syncthreads();
            #pragma unroll
            for (int f = 0; f < 50; f++) {
                float v = sm.s3.val[ty][f];
                ull vp = pk2(v, v);
                const ull* cp = (const ull*)&sm.s3.ctx[f][col0];
                a0 = f2fma(vp, cp[0], a0);
                a1 = f2fma(vp, cp[1], a1);
            }
        }
        float a, b, c, d;
        upk2(a0, a, b); upk2(a1, c, d);
        *(float4*)&out[(size_t)row * Dn + col0] = make_float4(a, b, c, d);
    }
}

extern "C" void kernel_launch(void* const* d_in, const int* in_sizes, int n_in,
                              void* d_out, int out_size)
{
    const float* values   = (const float*)d_in[0];
    const float* feat_emb = (const float*)d_in[1];
    const float* hid_emb  = (const float*)d_in[2];
    const float* Ww       = (const float*)d_in[3];
    const float* bw       = (const float*)d_in[4];
    const float* Wu       = (const float*)d_in[5];
    const float* mask     = (const float*)d_in[6];
    float* out            = (float*)d_out;

    fused_all<<<NB, 128>>>(values, feat_emb, hid_emb, Ww, bw, Wu, mask, out);
}

// round 11
// speedup vs baseline: 2.1781x; 1.3706x over previous
#include <cuda_runtime.h>
#include <cuda_bf16.h>
#include <math.h>

#define Fn 500
#define Hn 2000
#define FH 2500
#define Dn 64
#define Bn 4096
#define NW 80            // bitmask words per row
#define NJC 4            // j-chunks of 640

// Scratch
__device__ __align__(16) float g_U[Fn * 128];     // [P1=wu*a^2 | P2=wu*a]
__device__ __align__(16) float g_V[FH * 128];     // [b | b^2]
__device__ float g_B[FH];
__device__ __align__(16) float g_pre_f[Fn * Dn];
__device__ unsigned g_mbits[Fn * NW];
__device__ __align__(16) float g_ctx_part[NJC][Fn][Dn];
__device__ float g_ssum_part[Fn][NJC];
__device__ __align__(16) float g_ctx[Fn * Dn];
__device__ int g_maxa_bits = 0;   // idempotent across replays (same inputs)
__device__ int g_maxb_bits = 0;
__device__ float g_sink;          // keeps prefetch loads alive

typedef unsigned long long ull;
__device__ __forceinline__ ull pk2(float a, float b) {
    ull r; asm("mov.b64 %0, {%1,%2};" : "=l"(r) : "f"(a), "f"(b)); return r;
}
__device__ __forceinline__ void upk2(ull v, float& a, float& b) {
    asm("mov.b64 {%0,%1}, %2;" : "=f"(a), "=f"(b) : "l"(v));
}
__device__ __forceinline__ ull f2fma(ull a, ull b, ull c) {
    ull d; asm("fma.rn.f32x2 %0, %1, %2, %3;" : "=l"(d) : "l"(a), "l"(b), "l"(c)); return d;
}
__device__ __forceinline__ const float* full_row(const float* feat,
                                                 const float* hid, int j) {
    return (j < Fn) ? (feat + j * Dn) : (hid + (j - Fn) * Dn);
}

// ---------------------------------------------------------------------------
// K1: blk 0..63     : stream `values` through L2 (prefetch for k4)
//     blk 64..688   : pre_w rows -> V=[b,b^2], B_j, maxb          (625)
//     blk 689..813  : pre_f rows -> U, pre_f, maxa                (125)
//     blk 814..970  : mask -> bitmask (float4, MLP 8)             (157)
// ---------------------------------------------------------------------------
__global__ __launch_bounds__(256) void k1(const float* __restrict__ values,
                                          const float* __restrict__ feat,
                                          const float* __restrict__ hid,
                                          const float* __restrict__ Ww,
                                          const float* __restrict__ bw,
                                          const float* __restrict__ Wu,
                                          const float* __restrict__ mask)
{
    __shared__ float sx[4][Dn];
    __shared__ float s_red[8];
    __shared__ float s_rmax[8];

    const int blk  = blockIdx.x;
    const int tid  = threadIdx.x;
    const int g    = tid >> 6;
    const int a    = tid & 63;
    const int wid  = tid >> 5;
    const int lane = tid & 31;

    if (blk < 64) {
        // values prefetch: 512000 float4 over 64 blocks x 256 threads
        const float4* src = (const float4*)values;
        float s = 0.f;
        for (int idx = blk * 256 + tid; idx < 512000; idx += 64 * 256) {
            float4 v = __ldg(&src[idx]);
            s += (v.x + v.y) + (v.z + v.w);
        }
        if (s == 1.2345678e38f) g_sink = s;   // never true; keeps loads
    } else if (blk < 689) {
        const int row = (blk - 64) * 4 + g;             // j: 0..2499
        float v = (row < Fn) ? feat[row * Dn + a] : hid[(row - Fn) * Dn + a];
        sx[g][a] = v;
        __syncthreads();
        float bacc = 0.f;
        #pragma unroll
        for (int k = 0; k < Dn; k++)
            bacc += sx[g][k] * __ldg(&Ww[(Dn + k) * Dn + a]);
        const float wua = __ldg(&Wu[a]);
        const float b2 = bacc * bacc;
        g_V[row * 128 + a]      = bacc;
        g_V[row * 128 + 64 + a] = b2;
        float term = wua * (bacc - bacc * b2 * 0.33333334f);
        float mm = fabsf(bacc);
        #pragma unroll
        for (int off = 16; off > 0; off >>= 1) {
            term += __shfl_xor_sync(0xffffffffu, term, off);
            mm = fmaxf(mm, __shfl_xor_sync(0xffffffffu, mm, off));
        }
        if (lane == 0) { s_red[wid] = term; s_rmax[wid] = mm; }
        __syncthreads();
        if (tid < 4)
            g_B[(blk - 64) * 4 + tid] = s_red[2 * tid] + s_red[2 * tid + 1];
        if (tid == 0) {
            float mx = fmaxf(fmaxf(s_rmax[0], s_rmax[1]),
                             fmaxf(s_rmax[2], s_rmax[3]));
            mx = fmaxf(mx, fmaxf(fmaxf(s_rmax[4], s_rmax[5]),
                                 fmaxf(s_rmax[6], s_rmax[7])));
            atomicMax(&g_maxb_bits, __float_as_int(mx));
        }
    } else if (blk < 814) {
        const int row = (blk - 689) * 4 + g;            // i: 0..499
        sx[g][a] = feat[row * Dn + a];
        __syncthreads();
        float av = __ldg(&bw[a]);
        #pragma unroll
        for (int k = 0; k < Dn; k++)
            av += sx[g][k] * __ldg(&Ww[k * Dn + a]);
        const float wua = __ldg(&Wu[a]);
        g_pre_f[row * Dn + a]   = av;
        g_U[row * 128 + a]      = wua * av * av;
        g_U[row * 128 + 64 + a] = wua * av;
        float mm = fabsf(av);
        #pragma unroll
        for (int off = 16; off > 0; off >>= 1)
            mm = fmaxf(mm, __shfl_xor_sync(0xffffffffu, mm, off));
        if (lane == 0) s_rmax[wid] = mm;
        __syncthreads();
        if (tid == 0) {
            float mx = fmaxf(fmaxf(s_rmax[0], s_rmax[1]),
                             fmaxf(s_rmax[2], s_rmax[3]));
            mx = fmaxf(mx, fmaxf(fmaxf(s_rmax[4], s_rmax[5]),
                                 fmaxf(s_rmax[6], s_rmax[7])));
            atomicMax(&g_maxa_bits, __float_as_int(mx));
        }
    } else {
        // bitmask: one 32-bit word per thread via 8 x float4 (MLP 8)
        const int gw = (blk - 814) * 256 + tid;         // word index
        if (gw < Fn * NW) {
            const int i = gw / NW;
            const int w = gw - i * NW;
            const int j0 = w * 32;
            const float* mrow = mask + (size_t)i * FH;
            unsigned word = 0;
            if (j0 + 32 <= FH) {
                const float4* m4 = (const float4*)(mrow + j0);
                #pragma unroll
                for (int q = 0; q < 8; q++) {
                    float4 v = __ldg(&m4[q]);
                    if (v.x != 0.f) word |= (1u << (q * 4 + 0));
                    if (v.y != 0.f) word |= (1u << (q * 4 + 1));
                    if (v.z != 0.f) word |= (1u << (q * 4 + 2));
                    if (v.w != 0.f) word |= (1u << (q * 4 + 3));
                }
            } else {
                for (int t = 0; t < 32; t++) {
                    int j = j0 + t;
                    if (j < FH && __ldg(&mrow[j]) != 0.0f) word |= (1u << t);
                }
            }
            g_mbits[gw] = word;
        }
    }
}

// ---------------------------------------------------------------------------
// K2: 2000 blocks = 500 i x 4 j-chunks. (verbatim R9 — measured fast)
// ---------------------------------------------------------------------------
__global__ __launch_bounds__(128) void k2(const float* __restrict__ feat,
                                          const float* __restrict__ hid,
                                          const float* __restrict__ Wu)
{
    __shared__ __align__(16) float s_U[128];
    __shared__ __align__(16) float s_pf[Dn];
    __shared__ __align__(16) float s_wu[Dn];
    __shared__ unsigned s_words[20];
    __shared__ unsigned short s_jlist[640];
    __shared__ float s_elist[640];
    __shared__ int   s_warpbase[5];
    __shared__ float s_wsum[4];
    __shared__ float s_part[2][Dn];
    __shared__ float s_swu;
    __shared__ int   s_exact;

    const int i    = blockIdx.x >> 2;
    const int jc   = blockIdx.x & 3;
    const int jbase = jc * 640;
    const int tid  = threadIdx.x;
    const int wid  = tid >> 5;
    const int lane = tid & 31;

    s_U[tid] = g_U[i * 128 + tid];
    if (tid < 20) s_words[tid] = g_mbits[i * NW + jc * 20 + tid];
    if (tid < Dn) {
        s_pf[tid] = g_pre_f[i * Dn + tid];
        s_wu[tid] = __ldg(&Wu[tid]);
    }
    __syncthreads();

    if (wid == 0) {
        float s = fabsf(s_wu[lane]) + fabsf(s_wu[lane + 32]);
        #pragma unroll
        for (int off = 16; off > 0; off >>= 1)
            s += __shfl_xor_sync(0xffffffffu, s, off);
        if (lane == 0) s_swu = s;
    }
    __syncthreads();
    if (tid == 0) {
        float bnd = __int_as_float(g_maxa_bits) + __int_as_float(g_maxb_bits);
        float b5 = bnd * bnd; b5 = b5 * b5 * bnd;
        s_exact = (0.1333334f * b5 * s_swu >= 1e-4f) ? 1 : 0;
    }

    unsigned flags = 0;
    #pragma unroll
    for (int c = 0; c < 5; c++) {
        const int jl = c * 128 + tid;
        const bool act = ((s_words[jl >> 5] >> (jl & 31)) & 1u) &&
                         (jbase + jl < FH);
        if (act) flags |= (1u << c);
    }
    const int cl = __popc(flags);
    int inc = cl;
    #pragma unroll
    for (int off = 1; off < 32; off <<= 1) {
        int v = __shfl_up_sync(0xffffffffu, inc, off);
        if (lane >= off) inc += v;
    }
    if (lane == 31) s_warpbase[wid + 1] = inc;
    __syncthreads();
    if (tid == 0) {
        s_warpbase[0] = 0;
        #pragma unroll
        for (int w = 1; w <= 4; w++) s_warpbase[w] += s_warpbase[w - 1];
    }
    __syncthreads();
    {
        int off = s_warpbase[wid] + inc - cl;
        #pragma unroll
        for (int c = 0; c < 5; c++)
            if ((flags >> c) & 1u)
                s_jlist[off++] = (unsigned short)(c * 128 + tid);
    }
    __syncthreads();
    const int cnt = s_warpbase[4];

    float wsum = 0.f;
    if (!s_exact) {
        const ull* P1u = (const ull*)s_U;
        const ull* P2u = (const ull*)(s_U + 64);
        for (int m = tid; m < cnt; m += 128) {
            const int j = jbase + (int)s_jlist[m];
            const float4* vr = (const float4*)(g_V + j * 128);
            ull acc = 0ull;
            #pragma unroll
            for (int q = 0; q < 16; q++) {
                float4 b4 = __ldg(vr + q);
                ull b01 = pk2(b4.x, b4.y);
                ull b23 = pk2(b4.z, b4.w);
                ull t01 = f2fma(P2u[2 * q],     b01, P1u[2 * q]);
                ull t23 = f2fma(P2u[2 * q + 1], b23, P1u[2 * q + 1]);
                acc = f2fma(t01, b01, acc);
                acc = f2fma(t23, b23, acc);
            }
            float d0, d1; upk2(acc, d0, d1);
            float e = __expf(__ldg(&g_B[j]) - (d0 + d1));
            s_elist[m] = e;
            wsum += e;
        }
    } else {
        for (int m = tid; m < cnt; m += 128) {
            const int j = jbase + (int)s_jlist[m];
            const float* vr = g_V + j * 128;
            float s = 0.f;
            for (int k = 0; k < Dn; k++)
                s += tanhf(s_pf[k] + vr[k]) * s_wu[k];
            float e = expf(s);
            s_elist[m] = e;
            wsum += e;
        }
    }
    #pragma unroll
    for (int off = 16; off > 0; off >>= 1)
        wsum += __shfl_xor_sync(0xffffffffu, wsum, off);
    if (lane == 0) s_wsum[wid] = wsum;
    __syncthreads();
    if (tid == 0)
        g_ssum_part[i][jc] = (s_wsum[0] + s_wsum[1]) + (s_wsum[2] + s_wsum[3]);

    {
        const int gg = tid >> 6;
        const int k  = tid & 63;
        float a0 = 0.f, a1 = 0.f, a2 = 0.f, a3 = 0.f;
        float a4 = 0.f, a5 = 0.f, a6 = 0.f, a7 = 0.f;
        int m = gg;
        for (; m + 14 < cnt; m += 16) {
            a0 += s_elist[m]      * __ldg(full_row(feat, hid, jbase + (int)s_jlist[m])      + k);
            a1 += s_elist[m + 2]  * __ldg(full_row(feat, hid, jbase + (int)s_jlist[m + 2])  + k);
            a2 += s_elist[m + 4]  * __ldg(full_row(feat, hid, jbase + (int)s_jlist[m + 4])  + k);
            a3 += s_elist[m + 6]  * __ldg(full_row(feat, hid, jbase + (int)s_jlist[m + 6])  + k);
            a4 += s_elist[m + 8]  * __ldg(full_row(feat, hid, jbase + (int)s_jlist[m + 8])  + k);
            a5 += s_elist[m + 10] * __ldg(full_row(feat, hid, jbase + (int)s_jlist[m + 10]) + k);
            a6 += s_elist[m + 12] * __ldg(full_row(feat, hid, jbase + (int)s_jlist[m + 12]) + k);
            a7 += s_elist[m + 14] * __ldg(full_row(feat, hid, jbase + (int)s_jlist[m + 14]) + k);
        }
        for (; m < cnt; m += 2)
            a0 += s_elist[m] * __ldg(full_row(feat, hid, jbase + (int)s_jlist[m]) + k);
        s_part[gg][k] = ((a0 + a1) + (a2 + a3)) + ((a4 + a5) + (a6 + a7));
        __syncthreads();
        if (tid < Dn)
            g_ctx_part[jc][i][tid] = s_part[0][tid] + s_part[1][tid];
    }
}

// ---------------------------------------------------------------------------
// K3: reduce partials. 125 blocks x 256.
// ---------------------------------------------------------------------------
__global__ __launch_bounds__(256) void k3()
{
    const int i = blockIdx.x * 4 + (threadIdx.x >> 6);
    const int k = threadIdx.x & 63;
    float ss = (g_ssum_part[i][0] + g_ssum_part[i][1]) +
               (g_ssum_part[i][2] + g_ssum_part[i][3]);
    const float inv = (ss > 0.f) ? (1.0f / ss) : 1.0f;
    float c = (g_ctx_part[0][i][k] + g_ctx_part[1][i][k]) +
              (g_ctx_part[2][i][k] + g_ctx_part[3][i][k]);
    g_ctx[i * Dn + k] = c * inv;
}

// ---------------------------------------------------------------------------
// K4: out = values @ ctx. 256 blocks x 256 thr, 16 rows, double-buffered.
// ---------------------------------------------------------------------------
__global__ __launch_bounds__(256) void k4(const float* __restrict__ values,
                                          float* __restrict__ out)
{
    __shared__ __align__(16) float s_val[2][16][50];
    __shared__ __align__(16) float s_ctx[2][50][64];

    const int rb   = blockIdx.x;
    const int tid  = threadIdx.x;
    const int tx   = tid & 15;
    const int ty   = tid >> 4;          // 0..15 -> row
    const int col0 = tx * 4;
    const int row  = rb * 16 + ty;

    // loader assignments (fixed per thread)
    float2 vreg[2];
    float4 creg[4];
    const int q0 = tid, q1 = tid + 256;             // values float2 ids (<400)
    const int vr0 = q0 / 25, vc0 = q0 - vr0 * 25;
    const int vr1 = q1 / 25, vc1 = q1 - vr1 * 25;

    #define LOAD_TILE(t)                                                     \
        do {                                                                 \
            vreg[0] = *(const float2*)&values[(size_t)(rb * 16 + vr0) * Fn + \
                                              (t) * 50 + vc0 * 2];           \
            if (q1 < 400)                                                    \
                vreg[1] = *(const float2*)&values[(size_t)(rb * 16 + vr1) *  \
                                                  Fn + (t) * 50 + vc1 * 2];  \
            _Pragma("unroll")                                                \
            for (int u = 0; u < 4; u++) {                                    \
                int p = tid + u * 256;                                       \
                if (p < 800) {                                               \
                    int f = p >> 4, c4 = p & 15;                             \
                    creg[u] = *(const float4*)&g_ctx[((t) * 50 + f) * 64 +   \
                                                     c4 * 4];                \
                }                                                            \
            }                                                                \
        } while (0)

    #define STORE_TILE(buf)                                                  \
        do {                                                                 \
            *(float2*)&s_val[buf][vr0][vc0 * 2] = vreg[0];                   \
            if (q1 < 400) *(float2*)&s_val[buf][vr1][vc1 * 2] = vreg[1];     \
            _Pragma("unroll")                                                \
            for (int u = 0; u < 4; u++) {                                    \
                int p = tid + u * 256;                                       \
                if (p < 800) {                                               \
                    int f = p >> 4, c4 = p & 15;                             \
                    *(float4*)&s_ctx[buf][f][c4 * 4] = creg[u];              \
                }                                                            \
            }                                                                \
        } while (0)

    LOAD_TILE(0);
    STORE_TILE(0);
    __syncthreads();

    ull a0 = 0ull, a1 = 0ull;
    #pragma unroll
    for (int t = 0; t < 10; t++) {
        if (t + 1 < 10) LOAD_TILE(t + 1);
        const int b = t & 1;
        #pragma unroll
        for (int f = 0; f < 50; f++) {
            float v = s_val[b][ty][f];
            ull vp = pk2(v, v);
            const ull* cp = (const ull*)&s_ctx[b][f][col0];
            a0 = f2fma(vp, cp[0], a0);
            a1 = f2fma(vp, cp[1], a1);
        }
        __syncthreads();
        if (t + 1 < 10) {
            STORE_TILE((t + 1) & 1);
        }
        __syncthreads();
    }

    float a, b2, c, d;
    upk2(a0, a, b2); upk2(a1, c, d);
    *(float4*)&out[(size_t)row * Dn + col0] = make_float4(a, b2, c, d);
}

// ---------------------------------------------------------------------------
extern "C" void kernel_launch(void* const* d_in, const int* in_sizes, int n_in,
                              void* d_out, int out_size)
{
    const float* values   = (const float*)d_in[0];
    const float* feat_emb = (const float*)d_in[1];
    const float* hid_emb  = (const float*)d_in[2];
    const float* Ww       = (const float*)d_in[3];
    const float* bw       = (const float*)d_in[4];
    const float* Wu       = (const float*)d_in[5];
    const float* mask     = (const float*)d_in[6];
    float* out            = (float*)d_out;

    k1<<<971, 256>>>(values, feat_emb, hid_emb, Ww, bw, Wu, mask);
    k2<<<2000, 128>>>(feat_emb, hid_emb, Wu);
    k3<<<125, 256>>>();
    k4<<<256, 256>>>(values, out);
}